// round 4
// baseline (speedup 1.0000x reference)
#include <cuda_runtime.h>
#include <cuda_bf16.h>
#include <cstdint>
#include <cstddef>

// Problem constants
#define DIMc 1024
#define Hc   16
#define HDc  64
#define Bc   8
#define Nc   1024
#define SCALEc 0.125f      // HD^-0.5
#define CAPc   50.0f

// ---------------------------------------------------------------------------
// Scratch (__device__ globals; allocation in kernel_launch is forbidden)
// ---------------------------------------------------------------------------
__device__ float g_q [(size_t)Bc * Hc * Nc * HDc];   // [B,H,N,HD]
__device__ float g_k [(size_t)Bc * Hc * Nc * HDc];
__device__ float g_v [(size_t)Bc * Hc * Nc * HDc];
__device__ float g_ao[(size_t)Bc * Nc * DIMc];       // [B,N,DIM]
__device__ unsigned char g_mask[(size_t)Nc * Nc];    // canonical 1-byte mask
__device__ int g_maskmode;                           // 1 = source is 1-byte, 0 = 4-byte

// ---------------------------------------------------------------------------
// Paired-bf16 helpers.  x = hi + lo with hi = bf16(x), lo = bf16(x - hi).
// Products use hi*hi + hi*lo + lo*hi (3 MMAs) -> ~2^-18 effective precision.
// ---------------------------------------------------------------------------
__device__ __forceinline__ unsigned pack2(float x, float y) {
    __nv_bfloat162 t = __floats2bfloat162_rn(x, y);
    return *reinterpret_cast<unsigned*>(&t);
}
__device__ __forceinline__ float bfhi(float x) {
    return __bfloat162float(__float2bfloat16_rn(x));
}

__device__ __forceinline__ void mma16(float* c, const unsigned* a, unsigned b0, unsigned b1) {
    asm volatile(
        "mma.sync.aligned.m16n8k16.row.col.f32.bf16.bf16.f32 "
        "{%0,%1,%2,%3},{%4,%5,%6,%7},{%8,%9},{%0,%1,%2,%3};"
        : "+f"(c[0]), "+f"(c[1]), "+f"(c[2]), "+f"(c[3])
        : "r"(a[0]), "r"(a[1]), "r"(a[2]), "r"(a[3]), "r"(b0), "r"(b1));
}

// ---------------------------------------------------------------------------
// Mask normalization: detect element width, write canonical uint8 g_mask.
// Reference guarantees diag(mask)=True. Under byte reads, a 1-byte mask has
// all diag bytes nonzero; a 4-byte (int32 0/1 or float 0.0/1.0) mask has
// diag byte probes land on zero bytes for i%4!=0 (byte1 of any such element
// is 0x00 for both int32 1 and fp32 1.0f) -> detector cannot false-positive.
// ---------------------------------------------------------------------------
__global__ void mask_detect_kernel(const unsigned char* __restrict__ m) {
    __shared__ int ok;
    if (threadIdx.x == 0) ok = 1;
    __syncthreads();
    for (int i = threadIdx.x; i < Nc; i += blockDim.x)
        if (m[(size_t)i * (Nc + 1)] == 0) ok = 0;
    __syncthreads();
    if (threadIdx.x == 0) g_maskmode = ok;
}

__global__ void mask_convert_kernel(const unsigned char* __restrict__ mb) {
    int i = blockIdx.x * 256 + threadIdx.x;
    if (g_maskmode) {
        g_mask[i] = (mb[i] != 0);
    } else {
        const unsigned* mw = (const unsigned*)mb;   // int32 or float32: nonzero == true
        g_mask[i] = (mw[i] != 0);
    }
}

// ---------------------------------------------------------------------------
// GEMM: C = X @ W^T.  X:[M,K] row-major, W:[O,K] row-major.  Paired-bf16.
// MODE 0: single (W,C) pair, plain row-major C (output projection).
// MODE 1: fused QKV — blockIdx.z in {0,1,2} selects (Wq,g_q)/(Wk,g_k)/(Wv,g_v);
//         C scattered to [B,H,N,HD]. Same tile math either way.
// Block tile 128x128x32, 8 warps (4x2), warp tile 32x64, m16n8k16.
// ---------------------------------------------------------------------------
template <int MODE>
__global__ void __launch_bounds__(256)
gemm_bf16p_kernel(const float* __restrict__ X,
                  const float* __restrict__ W0, const float* __restrict__ W1,
                  const float* __restrict__ W2,
                  float* __restrict__ C0, float* __restrict__ C1,
                  float* __restrict__ C2, int M, int O, int K)
{
    // u32 = packed bf16 pair along k. 16 data u32 per row (32 k) + 4 pad.
    __shared__ unsigned Ah[128][20], Al[128][20], Bh[128][20], Bl[128][20];

    const float* W = W0;
    float*       C = C0;
    if (MODE == 1) {
        if (blockIdx.z == 1) { W = W1; C = C1; }
        else if (blockIdx.z == 2) { W = W2; C = C2; }
    }

    const int tid  = threadIdx.x;
    const int warp = tid >> 5;
    const int lane = tid & 31;
    const int g    = lane >> 2;
    const int tg   = lane & 3;
    const int wm   = (warp >> 1) * 32;
    const int wn   = (warp & 1) * 64;
    const int m0   = blockIdx.y * 128;
    const int o0   = blockIdx.x * 128;

    float acc[2][8][4];
#pragma unroll
    for (int mt = 0; mt < 2; mt++)
#pragma unroll
        for (int nt = 0; nt < 8; nt++)
#pragma unroll
            for (int i = 0; i < 4; i++) acc[mt][nt][i] = 0.0f;

    for (int k0 = 0; k0 < K; k0 += 32) {
#pragma unroll
        for (int i = 0; i < 4; i++) {
            int idx = tid + i * 256;      // float4 index 0..1023
            int r   = idx >> 3;           // 8 float4 per 32-float row
            int c4  = idx & 7;
            float4 va = *(const float4*)(X + (size_t)(m0 + r) * K + k0 + c4 * 4);
            Ah[r][c4 * 2    ] = pack2(va.x, va.y);
            Ah[r][c4 * 2 + 1] = pack2(va.z, va.w);
            Al[r][c4 * 2    ] = pack2(va.x - bfhi(va.x), va.y - bfhi(va.y));
            Al[r][c4 * 2 + 1] = pack2(va.z - bfhi(va.z), va.w - bfhi(va.w));
            float4 vb = *(const float4*)(W + (size_t)(o0 + r) * K + k0 + c4 * 4);
            Bh[r][c4 * 2    ] = pack2(vb.x, vb.y);
            Bh[r][c4 * 2 + 1] = pack2(vb.z, vb.w);
            Bl[r][c4 * 2    ] = pack2(vb.x - bfhi(vb.x), vb.y - bfhi(vb.y));
            Bl[r][c4 * 2 + 1] = pack2(vb.z - bfhi(vb.z), vb.w - bfhi(vb.w));
        }
        __syncthreads();

#pragma unroll
        for (int kc = 0; kc < 2; kc++) {
            unsigned ah[2][4], al[2][4], bh[8][2], bl[8][2];
#pragma unroll
            for (int mt = 0; mt < 2; mt++) {
                int r = wm + mt * 16;
                ah[mt][0] = Ah[r + g    ][kc * 8 + tg    ];
                ah[mt][1] = Ah[r + g + 8][kc * 8 + tg    ];
                ah[mt][2] = Ah[r + g    ][kc * 8 + tg + 4];
                ah[mt][3] = Ah[r + g + 8][kc * 8 + tg + 4];
                al[mt][0] = Al[r + g    ][kc * 8 + tg    ];
                al[mt][1] = Al[r + g + 8][kc * 8 + tg    ];
                al[mt][2] = Al[r + g    ][kc * 8 + tg + 4];
                al[mt][3] = Al[r + g + 8][kc * 8 + tg + 4];
            }
#pragma unroll
            for (int nt = 0; nt < 8; nt++) {
                bh[nt][0] = Bh[wn + nt * 8 + g][kc * 8 + tg    ];
                bh[nt][1] = Bh[wn + nt * 8 + g][kc * 8 + tg + 4];
                bl[nt][0] = Bl[wn + nt * 8 + g][kc * 8 + tg    ];
                bl[nt][1] = Bl[wn + nt * 8 + g][kc * 8 + tg + 4];
            }
#pragma unroll
            for (int mt = 0; mt < 2; mt++)
#pragma unroll
                for (int nt = 0; nt < 8; nt++) {
                    mma16(acc[mt][nt], ah[mt], bh[nt][0], bh[nt][1]);
                    mma16(acc[mt][nt], ah[mt], bl[nt][0], bl[nt][1]);
                    mma16(acc[mt][nt], al[mt], bh[nt][0], bh[nt][1]);
                }
        }
        __syncthreads();
    }

#pragma unroll
    for (int mt = 0; mt < 2; mt++) {
#pragma unroll
        for (int nt = 0; nt < 8; nt++) {
#pragma unroll
            for (int rr = 0; rr < 4; rr++) {
                int r = m0 + wm + mt * 16 + g + ((rr >= 2) ? 8 : 0);
                int c = o0 + wn + nt * 8 + tg * 2 + (rr & 1);
                float val = acc[mt][nt][rr];
                if (MODE == 0) {
                    C[(size_t)r * O + c] = val;
                } else {
                    int bb   = r >> 10;
                    int ntok = r & 1023;
                    int hh   = c >> 6;
                    int dd   = c & 63;
                    C[((((size_t)bb * Hc + hh) * Nc + ntok) << 6) + dd] = val;
                }
            }
        }
    }
}

// ---------------------------------------------------------------------------
// QKNorm + gathered 2D RoPE (fp32, in place on g_q/g_k). Warp per row.
// ---------------------------------------------------------------------------
__global__ void __launch_bounds__(128)
qknorm_rope_kernel(const float* __restrict__ qg, const float* __restrict__ kg,
                   const float* __restrict__ cost, const float* __restrict__ sint,
                   const int* __restrict__ ridx)
{
    int row  = blockIdx.x * 4 + (threadIdx.x >> 5);
    int lane = threadIdx.x & 31;
    int ntok = row & (Nc - 1);

    float* qr = g_q + (size_t)row * HDc;
    float* kr = g_k + (size_t)row * HDc;

    float q0 = qr[lane], q1 = qr[lane + 32];
    float k0 = kr[lane], k1 = kr[lane + 32];

    float sq = q0 * q0 + q1 * q1;
    float sk = k0 * k0 + k1 * k1;
#pragma unroll
    for (int off = 16; off >= 1; off >>= 1) {
        sq += __shfl_xor_sync(0xffffffffu, sq, off);
        sk += __shfl_xor_sync(0xffffffffu, sk, off);
    }
    float rq = rsqrtf(sq * (1.0f / 64.0f) + 1e-6f);
    float rk = rsqrtf(sk * (1.0f / 64.0f) + 1e-6f);
    q0 *= rq * qg[lane]; q1 *= rq * qg[lane + 32];
    k0 *= rk * kg[lane]; k1 *= rk * kg[lane + 32];

    int idx = ridx[ntok];
    if (idx >= 0) {
        const float* cr = cost + (size_t)idx * HDc;
        const float* sr = sint + (size_t)idx * HDc;
        float c0 = cr[lane], c1 = cr[lane + 32];
        float s0 = sr[lane], s1 = sr[lane + 32];
        float nq0 = q0 * c0 - q1 * s0;
        float nq1 = q1 * c1 + q0 * s1;
        float nk0 = k0 * c0 - k1 * s0;
        float nk1 = k1 * c1 + k0 * s1;
        q0 = nq0; q1 = nq1; k0 = nk0; k1 = nk1;
    }
    qr[lane] = q0; qr[lane + 32] = q1;
    kr[lane] = k0; kr[lane + 32] = k1;
}

// ---------------------------------------------------------------------------
// Flash attention, paired-bf16 MMAs. CTA = 64 q rows x (h,b); 4 warps.
// K stored as bf16 pairs along d; V stored TRANSPOSED as bf16 pairs along kv.
// P C-fragment pairs (cols 2tg,2tg+1) are exactly the A-fragment layout for
// m16n8k16 -> no cross-lane shuffles for PV.
// ---------------------------------------------------------------------------
__global__ void __launch_bounds__(128)
attn_kernel()
{
    __shared__ unsigned Kh[64][36], Kl[64][36];          // [kv][d-pairs]
    __shared__ unsigned short Vh[64][72], Vl[64][72];    // [d][kv] bf16, u32-pair view

    const int b  = blockIdx.z;
    const int h  = blockIdx.y;
    const int q0 = blockIdx.x * 64;
    const size_t base = ((size_t)b * Hc + h) * Nc * HDc;
    const float* qp = g_q + base;
    const float* kp = g_k + base;
    const float* vp = g_v + base;

    const int tid  = threadIdx.x;
    const int warp = tid >> 5;
    const int lane = tid & 31;
    const int g    = lane >> 2;
    const int tg   = lane & 3;
    const int wm   = warp * 16;

    // ---- stage Q (hi/lo pairs) through Kh/Kl, then into fragments ----
#pragma unroll
    for (int i = 0; i < 8; i++) {
        int idx = tid + i * 128;
        int r = idx >> 4, c4 = idx & 15;
        float4 v4 = *(const float4*)(qp + (size_t)(q0 + r) * HDc + c4 * 4);
        Kh[r][c4 * 2    ] = pack2(v4.x, v4.y);
        Kh[r][c4 * 2 + 1] = pack2(v4.z, v4.w);
        Kl[r][c4 * 2    ] = pack2(v4.x - bfhi(v4.x), v4.y - bfhi(v4.y));
        Kl[r][c4 * 2 + 1] = pack2(v4.z - bfhi(v4.z), v4.w - bfhi(v4.w));
    }
    __syncthreads();
    unsigned qh[4][4], ql[4][4];
#pragma unroll
    for (int kc = 0; kc < 4; kc++) {
        qh[kc][0] = Kh[wm + g    ][kc * 8 + tg    ];
        qh[kc][1] = Kh[wm + g + 8][kc * 8 + tg    ];
        qh[kc][2] = Kh[wm + g    ][kc * 8 + tg + 4];
        qh[kc][3] = Kh[wm + g + 8][kc * 8 + tg + 4];
        ql[kc][0] = Kl[wm + g    ][kc * 8 + tg    ];
        ql[kc][1] = Kl[wm + g + 8][kc * 8 + tg    ];
        ql[kc][2] = Kl[wm + g    ][kc * 8 + tg + 4];
        ql[kc][3] = Kl[wm + g + 8][kc * 8 + tg + 4];
    }
    __syncthreads();

    float oacc[8][4];
#pragma unroll
    for (int nt = 0; nt < 8; nt++)
#pragma unroll
        for (int i = 0; i < 4; i++) oacc[nt][i] = 0.0f;

    float m_i[2] = {-1e30f, -1e30f};
    float l_i[2] = {0.0f, 0.0f};
    const float icap = SCALEc * (1.0f / CAPc);
    const unsigned* Vh32 = (const unsigned*)&Vh[0][0];   // row stride 36 u32
    const unsigned* Vl32 = (const unsigned*)&Vl[0][0];

    for (int kv0 = 0; kv0 < Nc; kv0 += 64) {
        // ---- load K tile (pairs along d) and V tile (transposed) ----
#pragma unroll
        for (int i = 0; i < 8; i++) {
            int idx = tid + i * 128;
            int r = idx >> 4, c4 = idx & 15;
            float4 kk = *(const float4*)(kp + (size_t)(kv0 + r) * HDc + c4 * 4);
            Kh[r][c4 * 2    ] = pack2(kk.x, kk.y);
            Kh[r][c4 * 2 + 1] = pack2(kk.z, kk.w);
            Kl[r][c4 * 2    ] = pack2(kk.x - bfhi(kk.x), kk.y - bfhi(kk.y));
            Kl[r][c4 * 2 + 1] = pack2(kk.z - bfhi(kk.z), kk.w - bfhi(kk.w));
            float4 vv = *(const float4*)(vp + (size_t)(kv0 + r) * HDc + c4 * 4);
            float f[4] = {vv.x, vv.y, vv.z, vv.w};
#pragma unroll
            for (int j = 0; j < 4; j++) {
                int d = c4 * 4 + j;
                __nv_bfloat16 hv = __float2bfloat16_rn(f[j]);
                Vh[d][r] = *reinterpret_cast<unsigned short*>(&hv);
                __nv_bfloat16 lv = __float2bfloat16_rn(f[j] - __bfloat162float(hv));
                Vl[d][r] = *reinterpret_cast<unsigned short*>(&lv);
            }
        }
        __syncthreads();

        // ---- S = Q K^T ----
        float s[8][4];
#pragma unroll
        for (int nt = 0; nt < 8; nt++)
#pragma unroll
            for (int i = 0; i < 4; i++) s[nt][i] = 0.0f;

#pragma unroll
        for (int kc = 0; kc < 4; kc++) {
#pragma unroll
            for (int nt = 0; nt < 8; nt++) {
                unsigned bh0 = Kh[nt * 8 + g][kc * 8 + tg    ];
                unsigned bh1 = Kh[nt * 8 + g][kc * 8 + tg + 4];
                unsigned bl0 = Kl[nt * 8 + g][kc * 8 + tg    ];
                unsigned bl1 = Kl[nt * 8 + g][kc * 8 + tg + 4];
                mma16(s[nt], qh[kc], bh0, bh1);
                mma16(s[nt], qh[kc], bl0, bl1);
                mma16(s[nt], ql[kc], bh0, bh1);
            }
        }

        // ---- softcap + mask ----
        const int qr0 = q0 + wm + g;
#pragma unroll
        for (int nt = 0; nt < 8; nt++) {
#pragma unroll
            for (int rr = 0; rr < 4; rr++) {
                int qrow = qr0 + ((rr >= 2) ? 8 : 0);
                int kvc  = kv0 + nt * 8 + tg * 2 + (rr & 1);
                float sv = CAPc * tanhf(s[nt][rr] * icap);
                sv = g_mask[(size_t)qrow * Nc + kvc] ? sv : -1e30f;
                s[nt][rr] = sv;
            }
        }

        // ---- online softmax ----
        float tm0 = -1e30f, tm1 = -1e30f;
#pragma unroll
        for (int nt = 0; nt < 8; nt++) {
            tm0 = fmaxf(tm0, fmaxf(s[nt][0], s[nt][1]));
            tm1 = fmaxf(tm1, fmaxf(s[nt][2], s[nt][3]));
        }
        tm0 = fmaxf(tm0, __shfl_xor_sync(0xffffffffu, tm0, 1));
        tm0 = fmaxf(tm0, __shfl_xor_sync(0xffffffffu, tm0, 2));
        tm1 = fmaxf(tm1, __shfl_xor_sync(0xffffffffu, tm1, 1));
        tm1 = fmaxf(tm1, __shfl_xor_sync(0xffffffffu, tm1, 2));

        float mn0 = fmaxf(m_i[0], tm0);
        float mn1 = fmaxf(m_i[1], tm1);
        float cr0 = __expf(m_i[0] - mn0);
        float cr1 = __expf(m_i[1] - mn1);
        m_i[0] = mn0; m_i[1] = mn1;

        float ps0 = 0.0f, ps1 = 0.0f;
#pragma unroll
        for (int nt = 0; nt < 8; nt++) {
            s[nt][0] = __expf(s[nt][0] - mn0); ps0 += s[nt][0];
            s[nt][1] = __expf(s[nt][1] - mn0); ps0 += s[nt][1];
            s[nt][2] = __expf(s[nt][2] - mn1); ps1 += s[nt][2];
            s[nt][3] = __expf(s[nt][3] - mn1); ps1 += s[nt][3];
        }
        ps0 += __shfl_xor_sync(0xffffffffu, ps0, 1);
        ps0 += __shfl_xor_sync(0xffffffffu, ps0, 2);
        ps1 += __shfl_xor_sync(0xffffffffu, ps1, 1);
        ps1 += __shfl_xor_sync(0xffffffffu, ps1, 2);
        l_i[0] = l_i[0] * cr0 + ps0;
        l_i[1] = l_i[1] * cr1 + ps1;

#pragma unroll
        for (int nt = 0; nt < 8; nt++) {
            oacc[nt][0] *= cr0; oacc[nt][1] *= cr0;
            oacc[nt][2] *= cr1; oacc[nt][3] *= cr1;
        }

        // ---- O += P V (P pairs straight from C fragments) ----
#pragma unroll
        for (int kc = 0; kc < 4; kc++) {
            unsigned ph[4], pl[4];
            float p00 = s[2 * kc][0],     p01 = s[2 * kc][1];
            float p10 = s[2 * kc][2],     p11 = s[2 * kc][3];
            float p20 = s[2 * kc + 1][0], p21 = s[2 * kc + 1][1];
            float p30 = s[2 * kc + 1][2], p31 = s[2 * kc + 1][3];
            ph[0] = pack2(p00, p01); pl[0] = pack2(p00 - bfhi(p00), p01 - bfhi(p01));
            ph[1] = pack2(p10, p11); pl[1] = pack2(p10 - bfhi(p10), p11 - bfhi(p11));
            ph[2] = pack2(p20, p21); pl[2] = pack2(p20 - bfhi(p20), p21 - bfhi(p21));
            ph[3] = pack2(p30, p31); pl[3] = pack2(p30 - bfhi(p30), p31 - bfhi(p31));
#pragma unroll
            for (int nt = 0; nt < 8; nt++) {
                unsigned vh0 = Vh32[(nt * 8 + g) * 36 + kc * 8 + tg    ];
                unsigned vh1 = Vh32[(nt * 8 + g) * 36 + kc * 8 + tg + 4];
                unsigned vl0 = Vl32[(nt * 8 + g) * 36 + kc * 8 + tg    ];
                unsigned vl1 = Vl32[(nt * 8 + g) * 36 + kc * 8 + tg + 4];
                mma16(oacc[nt], ph, vh0, vh1);
                mma16(oacc[nt], ph, vl0, vl1);
                mma16(oacc[nt], pl, vh0, vh1);
            }
        }
        __syncthreads();
    }

    // ---- epilogue ----
    float il0 = 1.0f / l_i[0];
    float il1 = 1.0f / l_i[1];
#pragma unroll
    for (int nt = 0; nt < 8; nt++) {
#pragma unroll
        for (int rr = 0; rr < 4; rr++) {
            int qrow = q0 + wm + g + ((rr >= 2) ? 8 : 0);
            int d    = nt * 8 + tg * 2 + (rr & 1);
            g_ao[(size_t)(b * Nc + qrow) * DIMc + h * HDc + d] =
                oacc[nt][rr] * ((rr >= 2) ? il1 : il0);
        }
    }
}

// ---------------------------------------------------------------------------
// kernel_launch. Inputs: x, Wq, Wk, Wv, Wo, q_gamma, k_gamma, cos, sin,
//                        rope_indices, mask
// ---------------------------------------------------------------------------
extern "C" void kernel_launch(void* const* d_in, const int* in_sizes, int n_in,
                              void* d_out, int out_size)
{
    const float* x    = (const float*)d_in[0];
    const float* Wq   = (const float*)d_in[1];
    const float* Wk   = (const float*)d_in[2];
    const float* Wv   = (const float*)d_in[3];
    const float* Wo   = (const float*)d_in[4];
    const float* qg   = (const float*)d_in[5];
    const float* kg   = (const float*)d_in[6];
    const float* cost = (const float*)d_in[7];
    const float* sint = (const float*)d_in[8];
    const int*   ridx = (const int*)d_in[9];
    const unsigned char* maskraw = (const unsigned char*)d_in[10];
    float* out = (float*)d_out;

    float *gq, *gk, *gv, *gao;
    cudaGetSymbolAddress((void**)&gq,  g_q);
    cudaGetSymbolAddress((void**)&gk,  g_k);
    cudaGetSymbolAddress((void**)&gv,  g_v);
    cudaGetSymbolAddress((void**)&gao, g_ao);

    mask_detect_kernel<<<1, 256>>>(maskraw);
    mask_convert_kernel<<<(Nc * Nc) / 256, 256>>>(maskraw);

    const int M = Bc * Nc;                     // 8192
    dim3 gqkv(DIMc / 128, M / 128, 3);         // fused QKV: (8, 64, 3)
    dim3 gout(DIMc / 128, M / 128, 1);         // output projection

    gemm_bf16p_kernel<1><<<gqkv, 256>>>(x, Wq, Wk, Wv, gq, gk, gv, M, DIMc, DIMc);

    qknorm_rope_kernel<<<(Bc * Hc * Nc) / 4, 128>>>(qg, kg, cost, sint, ridx);

    attn_kernel<<<dim3(Nc / 64, Hc, Bc), 128>>>();

    gemm_bf16p_kernel<0><<<gout, 256>>>(gao, Wo, nullptr, nullptr, out, nullptr, nullptr,
                                        M, DIMc, DIMc);
}